// round 1
// baseline (speedup 1.0000x reference)
#include <cuda_runtime.h>
#include <cuda_bf16.h>
#include <math.h>

// Problem dims (MoE_78245714198529): B=2, T=2048 -> NT=4096 tokens,
// D=1024, E=8, F=2048, TOP_K=2 -> NP=8192 token-expert pairs.
#define NT 4096
#define DD 1024
#define EE 8
#define FF 2048
#define NP (NT * 2)

// ---------------- scratch (static device globals; no allocation) -----------
__device__ int   g_count[EE];
__device__ int   g_arows[EE * NT];   // per-expert bucket: source row (token) for up/gating GEMMs
__device__ int   g_crows[EE * NT];   // per-expert bucket: pairId (= 2*tok + k)
__device__ float g_pw[NP];           // normalized top-2 weight per pair
__device__ float g_G[(size_t)NP * FF];   // gating pre-act, later H (in place)
__device__ float g_U[(size_t)NP * FF];   // up pre-act
__device__ float g_O[(size_t)NP * DD];   // per-pair down output (weighted)

// ---------------- kernel 0: zero counts ------------------------------------
__global__ void zero_counts_kernel() {
    if (threadIdx.x < EE) g_count[threadIdx.x] = 0;
}

// ---------------- kernel 1: router + bucketing ------------------------------
// One block (256 thr) per token. 8 warps -> 8 expert logits.
__global__ void router_kernel(const float* __restrict__ x,
                              const float* __restrict__ Wr) {
    __shared__ float xs[DD];
    __shared__ float logits[EE];
    const int t = blockIdx.x;
    const int tid = threadIdx.x;
    const float* xr = x + (size_t)t * DD;
    // load x row (256 threads * float4 = 1024 floats)
    *(float4*)&xs[tid * 4] = *(const float4*)&xr[tid * 4];
    __syncthreads();

    const int w = tid >> 5, lane = tid & 31;
    float s = 0.f;
    #pragma unroll 8
    for (int d = lane; d < DD; d += 32) s += xs[d] * Wr[d * EE + w];
    #pragma unroll
    for (int o = 16; o; o >>= 1) s += __shfl_xor_sync(0xffffffffu, s, o);
    if (lane == 0) logits[w] = s;
    __syncthreads();

    if (tid == 0) {
        float mx = logits[0];
        #pragma unroll
        for (int e = 1; e < EE; e++) mx = fmaxf(mx, logits[e]);
        float p[EE], se = 0.f;
        #pragma unroll
        for (int e = 0; e < EE; e++) { p[e] = expf(logits[e] - mx); se += p[e]; }
        const float inv = 1.f / se;
        #pragma unroll
        for (int e = 0; e < EE; e++) p[e] *= inv;
        // top-2 (strict > matches jax tie-break: lowest index wins)
        int e0 = 0;
        #pragma unroll
        for (int e = 1; e < EE; e++) if (p[e] > p[e0]) e0 = e;
        int e1 = (e0 == 0) ? 1 : 0;
        #pragma unroll
        for (int e = 0; e < EE; e++) if (e != e0 && p[e] > p[e1]) e1 = e;
        // renormalize: softmax over the two top probabilities
        const float z = expf(p[e1] - p[e0]);          // <= 1, stable
        const float w0 = 1.f / (1.f + z);
        const float w1 = z / (1.f + z);
        g_pw[2 * t]     = w0;
        g_pw[2 * t + 1] = w1;
        int i0 = atomicAdd(&g_count[e0], 1);
        g_arows[e0 * NT + i0] = t;
        g_crows[e0 * NT + i0] = 2 * t;
        int i1 = atomicAdd(&g_count[e1], 1);
        g_arows[e1 * NT + i1] = t;
        g_crows[e1 * NT + i1] = 2 * t + 1;
    }
}

// ---------------- grouped gather-GEMM ---------------------------------------
// C[c_rows[i], :] = A[a_rows[i], :] @ B_e   for i in [0, count[e])
// BM=128, BN=128, BK=8, 256 threads, 8x8 micro-tile, double-buffered smem.
__global__ __launch_bounds__(256)
void gemm_gather_kernel(const float* __restrict__ A,
                        const float* __restrict__ Bbase,
                        float* __restrict__ C,
                        const int* __restrict__ a_rows_all,
                        const int* __restrict__ c_rows_all,
                        int K, int N, size_t b_stride, int lda, int ldc) {
    constexpr int BM = 128, BN = 128, BK = 8;
    const int e = blockIdx.z;
    const int M = g_count[e];
    const int m0 = blockIdx.y * BM;
    if (m0 >= M) return;
    const int n0 = blockIdx.x * BN;
    const float* B = Bbase + (size_t)e * b_stride;
    const int* arows = a_rows_all + e * NT;
    const int* crows = c_rows_all + e * NT;

    __shared__ float As[2][BK][BM];
    __shared__ float Bs[2][BK][BN];

    const int tid = threadIdx.x;
    const int tx = tid & 15, ty = tid >> 4;

    // A tile loader: thread -> (row = tid>>1, kvec = (tid&1)*4)
    const int a_r = tid >> 1;
    const int a_k = (tid & 1) * 4;
    const bool a_ok = (m0 + a_r) < M;
    const float* a_ptr = a_ok ? (A + (size_t)arows[m0 + a_r] * lda) : A;
    // B tile loader: thread -> (k = tid>>5, nvec = (tid&31)*4)
    const int b_k = tid >> 5;
    const int b_n = (tid & 31) * 4;
    const float* b_ptr = B + (size_t)b_k * N + n0 + b_n;

    float acc[8][8];
    #pragma unroll
    for (int i = 0; i < 8; i++)
        #pragma unroll
        for (int j = 0; j < 8; j++) acc[i][j] = 0.f;

    const int KT = K / BK;

    // prologue: stage 0
    float4 av = a_ok ? *(const float4*)(a_ptr + a_k) : make_float4(0, 0, 0, 0);
    As[0][a_k + 0][a_r] = av.x;
    As[0][a_k + 1][a_r] = av.y;
    As[0][a_k + 2][a_r] = av.z;
    As[0][a_k + 3][a_r] = av.w;
    *(float4*)&Bs[0][b_k][b_n] = *(const float4*)b_ptr;
    __syncthreads();

    int buf = 0;
    for (int kt = 0; kt < KT; kt++) {
        float4 av2, bv2;
        const bool more = (kt + 1) < KT;
        if (more) {
            const int kg = (kt + 1) * BK;
            av2 = a_ok ? *(const float4*)(a_ptr + kg + a_k) : make_float4(0, 0, 0, 0);
            bv2 = *(const float4*)(b_ptr + (size_t)kg * N);
        }
        #pragma unroll
        for (int k = 0; k < BK; k++) {
            float4 a0 = *(float4*)&As[buf][k][ty * 8];
            float4 a1 = *(float4*)&As[buf][k][ty * 8 + 4];
            float4 b0 = *(float4*)&Bs[buf][k][tx * 8];
            float4 b1 = *(float4*)&Bs[buf][k][tx * 8 + 4];
            float af[8] = {a0.x, a0.y, a0.z, a0.w, a1.x, a1.y, a1.z, a1.w};
            float bf[8] = {b0.x, b0.y, b0.z, b0.w, b1.x, b1.y, b1.z, b1.w};
            #pragma unroll
            for (int i = 0; i < 8; i++)
                #pragma unroll
                for (int j = 0; j < 8; j++)
                    acc[i][j] = fmaf(af[i], bf[j], acc[i][j]);
        }
        if (more) {
            const int nb = buf ^ 1;
            As[nb][a_k + 0][a_r] = av2.x;
            As[nb][a_k + 1][a_r] = av2.y;
            As[nb][a_k + 2][a_r] = av2.z;
            As[nb][a_k + 3][a_r] = av2.w;
            *(float4*)&Bs[nb][b_k][b_n] = bv2;
            __syncthreads();
            buf = nb;
        }
    }

    #pragma unroll
    for (int i = 0; i < 8; i++) {
        const int r = m0 + ty * 8 + i;
        if (r < M) {
            float* crow = C + (size_t)crows[r] * ldc + n0 + tx * 8;
            *(float4*)(crow + 0) = make_float4(acc[i][0], acc[i][1], acc[i][2], acc[i][3]);
            *(float4*)(crow + 4) = make_float4(acc[i][4], acc[i][5], acc[i][6], acc[i][7]);
        }
    }
}

// ---------------- kernel: H = w_pair * silu(G) * U (in place into g_G) ------
__global__ void silu_mul_kernel() {
    const size_t i = (size_t)blockIdx.x * blockDim.x + threadIdx.x;  // float4 index
    const int p = (int)(i / (FF / 4));
    const float w = g_pw[p];
    float4 g = ((const float4*)g_G)[i];
    float4 u = ((const float4*)g_U)[i];
    float4 h;
    h.x = w * (g.x / (1.f + expf(-g.x))) * u.x;
    h.y = w * (g.y / (1.f + expf(-g.y))) * u.y;
    h.z = w * (g.z / (1.f + expf(-g.z))) * u.z;
    h.w = w * (g.w / (1.f + expf(-g.w))) * u.w;
    ((float4*)g_G)[i] = h;
}

// ---------------- kernel: out[t] = O[2t] + O[2t+1] ---------------------------
__global__ void combine_kernel(float* __restrict__ out) {
    const size_t i = (size_t)blockIdx.x * blockDim.x + threadIdx.x;  // float4 index
    const size_t t = i / (DD / 4);
    const size_t c = i % (DD / 4);
    const float4 a = ((const float4*)g_O)[t * 2 * (DD / 4) + c];
    const float4 b = ((const float4*)g_O)[(t * 2 + 1) * (DD / 4) + c];
    ((float4*)out)[i] = make_float4(a.x + b.x, a.y + b.y, a.z + b.z, a.w + b.w);
}

// ---------------- launcher ---------------------------------------------------
extern "C" void kernel_launch(void* const* d_in, const int* in_sizes, int n_in,
                              void* d_out, int out_size) {
    const float* x  = (const float*)d_in[0];  // [2,2048,1024]
    const float* Wr = (const float*)d_in[1];  // [1024,8]
    const float* Wg = (const float*)d_in[2];  // [8,1024,2048]
    const float* Wu = (const float*)d_in[3];  // [8,1024,2048]
    const float* Wd = (const float*)d_in[4];  // [8,2048,1024]
    float* out = (float*)d_out;               // [2,2048,1024]

    zero_counts_kernel<<<1, 32>>>();
    router_kernel<<<NT, 256>>>(x, Wr);

    int* arows; int* crows;
    cudaGetSymbolAddress((void**)&arows, g_arows);
    cudaGetSymbolAddress((void**)&crows, g_crows);
    float* G; float* U; float* O;
    cudaGetSymbolAddress((void**)&G, g_G);
    cudaGetSymbolAddress((void**)&U, g_U);
    cudaGetSymbolAddress((void**)&O, g_O);

    // gating & up: C[pair] = x[tok] @ W[e]   (K=1024, N=2048)
    dim3 gridGU(FF / 128, NT / 128, EE);
    gemm_gather_kernel<<<gridGU, 256>>>(x, Wg, G, arows, crows,
                                        DD, FF, (size_t)DD * FF, DD, FF);
    gemm_gather_kernel<<<gridGU, 256>>>(x, Wu, U, arows, crows,
                                        DD, FF, (size_t)DD * FF, DD, FF);

    // H = w * silu(G) * U, in place into G
    silu_mul_kernel<<<(int)(((size_t)NP * FF / 4) / 256), 256>>>();

    // down: O[pair] = H[pair] @ Wd[e]   (K=2048, N=1024)
    dim3 gridD(DD / 128, NT / 128, EE);
    gemm_gather_kernel<<<gridD, 256>>>(G, Wd, O, crows, crows,
                                       FF, DD, (size_t)FF * DD, FF, DD);

    combine_kernel<<<(int)(((size_t)NT * DD / 4) / 256), 256>>>(out);
}

// round 3
// speedup vs baseline: 2.9318x; 2.9318x over previous
#include <cuda_runtime.h>
#include <cuda_bf16.h>
#include <math.h>
#include <stdint.h>

// Problem dims: B=2, T=2048 -> NT=4096 tokens, D=1024, E=8, F=2048, top-2 -> NP=8192 pairs.
#define NT 4096
#define DD 1024
#define EE 8
#define FF 2048
#define NP (NT * 2)

// ---------------- static scratch ----------------
__device__ int   g_count[EE];
__device__ int   g_arows[EE * NT];   // per-expert bucket: token row for A gather
__device__ int   g_crows[EE * NT];   // per-expert bucket: pairId (= 2*tok + k)
__device__ float g_pw[NP];
__device__ float g_G[(size_t)NP * FF];   // gating pre-act, then H in place
__device__ float g_U[(size_t)NP * FF];
__device__ float g_O[(size_t)NP * DD];

// ---------------- helpers ----------------
__device__ __forceinline__ uint32_t smem_u32(const void* p) {
    uint32_t a;
    asm("{ .reg .u64 t; cvta.to.shared.u64 t, %1; cvt.u32.u64 %0, t; }" : "=r"(a) : "l"(p));
    return a;
}
__device__ __forceinline__ uint32_t f2tf(float f) {
    uint32_t r;
    asm("cvt.rna.tf32.f32 %0, %1;" : "=r"(r) : "f"(f));
    return r;
}
#define CP_ASYNC16(sdst, gsrc) \
    asm volatile("cp.async.cg.shared.global [%0], [%1], 16;" :: "r"(sdst), "l"(gsrc) : "memory")
#define CP_COMMIT() asm volatile("cp.async.commit_group;" ::: "memory")
#define CP_WAIT1()  asm volatile("cp.async.wait_group 1;" ::: "memory")

__device__ __forceinline__ void mma_tf32(float* c, const uint32_t* a, uint32_t b0, uint32_t b1) {
    asm volatile(
        "mma.sync.aligned.m16n8k8.row.col.f32.tf32.tf32.f32 "
        "{%0,%1,%2,%3}, {%4,%5,%6,%7}, {%8,%9}, {%0,%1,%2,%3};"
        : "+f"(c[0]), "+f"(c[1]), "+f"(c[2]), "+f"(c[3])
        : "r"(a[0]), "r"(a[1]), "r"(a[2]), "r"(a[3]), "r"(b0), "r"(b1));
}

// ---------------- router path ----------------
__global__ void zero_counts_kernel() {
    if (threadIdx.x < EE) g_count[threadIdx.x] = 0;
}

__global__ void router_kernel(const float* __restrict__ x,
                              const float* __restrict__ Wr) {
    __shared__ float xs[DD];
    __shared__ float logits[EE];
    const int t = blockIdx.x;
    const int tid = threadIdx.x;
    const float* xr = x + (size_t)t * DD;
    *(float4*)&xs[tid * 4] = *(const float4*)&xr[tid * 4];
    __syncthreads();

    const int w = tid >> 5, lane = tid & 31;
    float s = 0.f;
    #pragma unroll 8
    for (int d = lane; d < DD; d += 32) s += xs[d] * Wr[d * EE + w];
    #pragma unroll
    for (int o = 16; o; o >>= 1) s += __shfl_xor_sync(0xffffffffu, s, o);
    if (lane == 0) logits[w] = s;
    __syncthreads();

    if (tid == 0) {
        float mx = logits[0];
        #pragma unroll
        for (int e = 1; e < EE; e++) mx = fmaxf(mx, logits[e]);
        float p[EE], se = 0.f;
        #pragma unroll
        for (int e = 0; e < EE; e++) { p[e] = expf(logits[e] - mx); se += p[e]; }
        const float inv = 1.f / se;
        #pragma unroll
        for (int e = 0; e < EE; e++) p[e] *= inv;
        int e0 = 0;
        #pragma unroll
        for (int e = 1; e < EE; e++) if (p[e] > p[e0]) e0 = e;
        int e1 = (e0 == 0) ? 1 : 0;
        #pragma unroll
        for (int e = 0; e < EE; e++) if (e != e0 && p[e] > p[e1]) e1 = e;
        const float z = expf(p[e1] - p[e0]);
        g_pw[2 * t]     = 1.f / (1.f + z);
        g_pw[2 * t + 1] = z / (1.f + z);
        int i0 = atomicAdd(&g_count[e0], 1);
        g_arows[e0 * NT + i0] = t;
        g_crows[e0 * NT + i0] = 2 * t;
        int i1 = atomicAdd(&g_count[e1], 1);
        g_arows[e1 * NT + i1] = t;
        g_crows[e1 * NT + i1] = 2 * t + 1;
    }
}

// ---------------- tensor-core grouped gather-GEMM -----------------------------
// C[crows[i], 0:N] = A[arows[i], 0:K] @ B_e[0:K, 0:N]  (B row-major K x N).
// BM=128, BN=128, BK=16, 3-stage cp.async, 8 warps x (32x64) via m16n8k8 tf32.
#define BK 16
#define NSTG 3
#define LDA_S 20          // A smem row stride (floats), 16B aligned, conflict-free
#define LDB_S 132         // B smem row stride (floats)
#define A_STG (128 * LDA_S)
#define B_STG (BK * LDB_S)
#define GEMM_SMEM ((NSTG * (A_STG + B_STG)) * 4)

__global__ __launch_bounds__(256, 2)
void gemm_tc_kernel(const float* __restrict__ A,
                    const float* __restrict__ Bbase,
                    float* __restrict__ C,
                    const int* __restrict__ a_rows_all,
                    const int* __restrict__ c_rows_all,
                    int K, int N, size_t b_stride, int lda, int ldc) {
    const int e = blockIdx.z;
    const int M = g_count[e];
    const int m0 = blockIdx.y * 128;
    if (m0 >= M) return;
    const int n0 = blockIdx.x * 128;
    const float* B = Bbase + (size_t)e * b_stride;
    const int* arows = a_rows_all + e * NT;
    const int* crows = c_rows_all + e * NT;

    extern __shared__ float smem[];
    float* As = smem;                       // [NSTG][128][LDA_S]
    float* Bs = smem + NSTG * A_STG;        // [NSTG][BK][LDB_S]

    const int tid = threadIdx.x;
    const int wid = tid >> 5, lane = tid & 31;
    const int g = lane >> 2, t4 = lane & 3;
    const int wm = wid & 3, wn = wid >> 2;  // warp tile: rows wm*32, cols wn*64

    // --- loader setup: A = 2 float4/thread, B = 2 float4/thread per stage ---
    const int ar1 = min(m0 + (tid >> 2), M - 1);
    const int ar2 = min(m0 + (tid >> 2) + 64, M - 1);
    const float* ap1 = A + (size_t)arows[ar1] * lda + (tid & 3) * 4;
    const float* ap2 = A + (size_t)arows[ar2] * lda + (tid & 3) * 4;
    const float* bp1 = B + (size_t)(tid >> 5) * N + n0 + (tid & 31) * 4;
    const float* bp2 = bp1 + (size_t)8 * N;
    const uint32_t sa1 = smem_u32(As) + (((tid >> 2) * LDA_S + (tid & 3) * 4)) * 4;
    const uint32_t sa2 = sa1 + 64 * LDA_S * 4;
    const uint32_t sb1 = smem_u32(Bs) + (((tid >> 5) * LDB_S + (tid & 31) * 4)) * 4;
    const uint32_t sb2 = sb1 + 8 * LDB_S * 4;

    const int KT = K / BK;

    // prologue: stages 0, 1
    #pragma unroll
    for (int s = 0; s < NSTG - 1; s++) {
        const int kof = s * BK;
        CP_ASYNC16(sa1 + s * A_STG * 4, ap1 + kof);
        CP_ASYNC16(sa2 + s * A_STG * 4, ap2 + kof);
        CP_ASYNC16(sb1 + s * B_STG * 4, bp1 + (size_t)kof * N);
        CP_ASYNC16(sb2 + s * B_STG * 4, bp2 + (size_t)kof * N);
        CP_COMMIT();
    }

    float acc[2][8][4];
    #pragma unroll
    for (int i = 0; i < 2; i++)
        #pragma unroll
        for (int j = 0; j < 8; j++)
            #pragma unroll
            for (int q = 0; q < 4; q++) acc[i][j][q] = 0.f;

    for (int kt = 0; kt < KT; kt++) {
        CP_WAIT1();
        __syncthreads();
        // issue stage kt + NSTG - 1 (slot reuse is safe: computed in iter kt-1)
        {
            const int kn = kt + NSTG - 1;
            const int s = kn % NSTG;
            if (kn < KT) {
                const int kof = kn * BK;
                CP_ASYNC16(sa1 + s * A_STG * 4, ap1 + kof);
                CP_ASYNC16(sa2 + s * A_STG * 4, ap2 + kof);
                CP_ASYNC16(sb1 + s * B_STG * 4, bp1 + (size_t)kof * N);
                CP_ASYNC16(sb2 + s * B_STG * 4, bp2 + (size_t)kof * N);
            }
            CP_COMMIT();
        }
        const float* as = As + (kt % NSTG) * A_STG;
        const float* bs = Bs + (kt % NSTG) * B_STG;
        #pragma unroll
        for (int kk = 0; kk < BK; kk += 8) {
            uint32_t af[2][4];
            #pragma unroll
            for (int mf = 0; mf < 2; mf++) {
                const int rb = wm * 32 + mf * 16 + g;
                af[mf][0] = f2tf(as[rb * LDA_S + kk + t4]);
                af[mf][1] = f2tf(as[(rb + 8) * LDA_S + kk + t4]);
                af[mf][2] = f2tf(as[rb * LDA_S + kk + t4 + 4]);
                af[mf][3] = f2tf(as[(rb + 8) * LDA_S + kk + t4 + 4]);
            }
            #pragma unroll
            for (int nf = 0; nf < 8; nf++) {
                const int cb = wn * 64 + nf * 8 + g;
                const uint32_t b0 = f2tf(bs[(kk + t4) * LDB_S + cb]);
                const uint32_t b1 = f2tf(bs[(kk + t4 + 4) * LDB_S + cb]);
                mma_tf32(acc[0][nf], af[0], b0, b1);
                mma_tf32(acc[1][nf], af[1], b0, b1);
            }
        }
    }

    // epilogue: scatter via crows
    #pragma unroll
    for (int mf = 0; mf < 2; mf++) {
        const int r0 = m0 + wm * 32 + mf * 16 + g;
        const int r1 = r0 + 8;
        float* c0p = (r0 < M) ? (C + (size_t)crows[r0] * ldc) : nullptr;
        float* c1p = (r1 < M) ? (C + (size_t)crows[r1] * ldc) : nullptr;
        #pragma unroll
        for (int nf = 0; nf < 8; nf++) {
            const int cc = n0 + wn * 64 + nf * 8 + t4 * 2;
            if (c0p) *(float2*)(c0p + cc) = make_float2(acc[mf][nf][0], acc[mf][nf][1]);
            if (c1p) *(float2*)(c1p + cc) = make_float2(acc[mf][nf][2], acc[mf][nf][3]);
        }
    }
}

// ---------------- H = w_pair * silu(G) * U (in place into g_G) ----------------
__global__ void silu_mul_kernel() {
    const size_t i = (size_t)blockIdx.x * blockDim.x + threadIdx.x;
    const int p = (int)(i / (FF / 4));
    const float w = g_pw[p];
    float4 gv = ((const float4*)g_G)[i];
    float4 uv = ((const float4*)g_U)[i];
    float4 h;
    h.x = w * (gv.x / (1.f + __expf(-gv.x))) * uv.x;
    h.y = w * (gv.y / (1.f + __expf(-gv.y))) * uv.y;
    h.z = w * (gv.z / (1.f + __expf(-gv.z))) * uv.z;
    h.w = w * (gv.w / (1.f + __expf(-gv.w))) * uv.w;
    ((float4*)g_G)[i] = h;
}

// ---------------- combine: out[t] = O[2t] + O[2t+1] ---------------------------
__global__ void combine_kernel(float* __restrict__ out) {
    const size_t i = (size_t)blockIdx.x * blockDim.x + threadIdx.x;
    const size_t t = i / (DD / 4);
    const size_t c = i % (DD / 4);
    const float4 a = ((const float4*)g_O)[t * 2 * (DD / 4) + c];
    const float4 b = ((const float4*)g_O)[(t * 2 + 1) * (DD / 4) + c];
    ((float4*)out)[i] = make_float4(a.x + b.x, a.y + b.y, a.z + b.z, a.w + b.w);
}

// ---------------- launcher ---------------------------------------------------
extern "C" void kernel_launch(void* const* d_in, const int* in_sizes, int n_in,
                              void* d_out, int out_size) {
    const float* x  = (const float*)d_in[0];  // [2,2048,1024]
    const float* Wr = (const float*)d_in[1];  // [1024,8]
    const float* Wg = (const float*)d_in[2];  // [8,1024,2048]
    const float* Wu = (const float*)d_in[3];  // [8,1024,2048]
    const float* Wd = (const float*)d_in[4];  // [8,2048,1024]
    float* out = (float*)d_out;

    cudaFuncSetAttribute(gemm_tc_kernel,
                         cudaFuncAttributeMaxDynamicSharedMemorySize, GEMM_SMEM);

    int* arows; int* crows;
    cudaGetSymbolAddress((void**)&arows, g_arows);
    cudaGetSymbolAddress((void**)&crows, g_crows);
    float* G; float* U; float* O;
    cudaGetSymbolAddress((void**)&G, g_G);
    cudaGetSymbolAddress((void**)&U, g_U);
    cudaGetSymbolAddress((void**)&O, g_O);

    zero_counts_kernel<<<1, 32>>>();
    router_kernel<<<NT, 256>>>(x, Wr);

    // gating & up: C[pair] = x[tok] @ W[e]  (K=1024, N=2048)
    dim3 gridGU(FF / 128, NT / 128, EE);
    gemm_tc_kernel<<<gridGU, 256, GEMM_SMEM>>>(x, Wg, G, arows, crows,
                                               DD, FF, (size_t)DD * FF, DD, FF);
    gemm_tc_kernel<<<gridGU, 256, GEMM_SMEM>>>(x, Wu, U, arows, crows,
                                               DD, FF, (size_t)DD * FF, DD, FF);

    silu_mul_kernel<<<(int)(((size_t)NP * FF / 4) / 256), 256>>>();

    // down: O[pair] = H[pair] @ Wd[e]  (K=2048, N=1024)
    dim3 gridD(DD / 128, NT / 128, EE);
    gemm_tc_kernel<<<gridD, 256, GEMM_SMEM>>>(G, Wd, O, crows, crows,
                                              FF, DD, (size_t)FF * DD, FF, DD);

    combine_kernel<<<(int)(((size_t)NT * DD / 4) / 256), 256>>>(out);
}

// round 4
// speedup vs baseline: 3.3043x; 1.1271x over previous
#include <cuda_runtime.h>
#include <cuda_bf16.h>
#include <math.h>
#include <stdint.h>

// Problem dims: B=2, T=2048 -> NT=4096 tokens, D=1024, E=8, F=2048, top-2 -> NP=8192 pairs.
#define NT 4096
#define DD 1024
#define EE 8
#define FF 2048
#define NP (NT * 2)

#define BK 16
#define NSTG 4

// GU kernel tiles: BM=128, BN=128, warp tile 64x32, dual accumulators (G,U)
#define A_SZ   (128 * 20)          // floats per A stage (row stride 20)
#define BGU_SZ (BK * 136)          // floats per B stage (row stride 136)
#define STG_GU (A_SZ + 2 * BGU_SZ) // 6912 floats
#define GU_SMEM (NSTG * STG_GU * 4)

// DN kernel tiles: BM=128, BN=256, warp tile 64x64
#define BDN_SZ (BK * 264)
#define STG_DN (A_SZ + BDN_SZ)     // 6784 floats
#define DN_SMEM (NSTG * STG_DN * 4)

#define KT_GU (DD / BK)   // 64
#define KT_DN (FF / BK)   // 128

// ---------------- static scratch (tf32-bit patterns stored as float) --------
__device__ int   g_count[EE];
__device__ int   g_off[EE];
__device__ int   g_arows[EE * NT];
__device__ int   g_crows[EE * NT];
__device__ float g_pw[NP];
__device__ float g_X [(size_t)NT * DD];        // x, tf32 bits
__device__ float g_Wg[(size_t)EE * DD * FF];   // tf32 bits
__device__ float g_Wu[(size_t)EE * DD * FF];
__device__ float g_Wd[(size_t)EE * FF * DD];
__device__ float g_H [(size_t)NP * FF];        // compact (expert-offset) H rows, tf32 bits
__device__ float g_O [(size_t)NP * DD];        // fp32

// ---------------- helpers ----------------
__device__ __forceinline__ uint32_t smem_u32(const void* p) {
    uint32_t a;
    asm("{ .reg .u64 t; cvta.to.shared.u64 t, %1; cvt.u32.u64 %0, t; }" : "=r"(a) : "l"(p));
    return a;
}
__device__ __forceinline__ uint32_t f2tf(float f) {
    uint32_t r;
    asm("cvt.rna.tf32.f32 %0, %1;" : "=r"(r) : "f"(f));
    return r;
}
#define CP_ASYNC16(sdst, gsrc) \
    asm volatile("cp.async.cg.shared.global [%0], [%1], 16;" :: "r"(sdst), "l"(gsrc) : "memory")
#define CP_COMMIT() asm volatile("cp.async.commit_group;" ::: "memory")
#define CP_WAIT2()  asm volatile("cp.async.wait_group 2;" ::: "memory")

__device__ __forceinline__ void mma_tf32(float* c, const uint32_t* a, uint32_t b0, uint32_t b1) {
    asm volatile(
        "mma.sync.aligned.m16n8k8.row.col.f32.tf32.tf32.f32 "
        "{%0,%1,%2,%3}, {%4,%5,%6,%7}, {%8,%9}, {%0,%1,%2,%3};"
        : "+f"(c[0]), "+f"(c[1]), "+f"(c[2]), "+f"(c[3])
        : "r"(a[0]), "r"(a[1]), "r"(a[2]), "r"(a[3]), "r"(b0), "r"(b1));
}
__device__ __forceinline__ uint32_t ldsf(const float* p) {
    return __float_as_uint(*p);
}

// ---------------- tf32 convert pass ----------------
__global__ void cvt_kernel(const float4* __restrict__ in, float4* __restrict__ out) {
    const size_t i = (size_t)blockIdx.x * blockDim.x + threadIdx.x;
    float4 v = in[i];
    float4 o;
    o.x = __uint_as_float(f2tf(v.x));
    o.y = __uint_as_float(f2tf(v.y));
    o.z = __uint_as_float(f2tf(v.z));
    o.w = __uint_as_float(f2tf(v.w));
    out[i] = o;
}

// ---------------- router path ----------------
__global__ void zero_counts_kernel() {
    if (threadIdx.x < EE) g_count[threadIdx.x] = 0;
}

__global__ void router_kernel(const float* __restrict__ x,
                              const float* __restrict__ Wr) {
    __shared__ float xs[DD];
    __shared__ float logits[EE];
    const int t = blockIdx.x;
    const int tid = threadIdx.x;
    const float* xr = x + (size_t)t * DD;
    *(float4*)&xs[tid * 4] = *(const float4*)&xr[tid * 4];
    __syncthreads();

    const int w = tid >> 5, lane = tid & 31;
    float s = 0.f;
    #pragma unroll 8
    for (int d = lane; d < DD; d += 32) s += xs[d] * Wr[d * EE + w];
    #pragma unroll
    for (int o = 16; o; o >>= 1) s += __shfl_xor_sync(0xffffffffu, s, o);
    if (lane == 0) logits[w] = s;
    __syncthreads();

    if (tid == 0) {
        float mx = logits[0];
        #pragma unroll
        for (int e = 1; e < EE; e++) mx = fmaxf(mx, logits[e]);
        float p[EE], se = 0.f;
        #pragma unroll
        for (int e = 0; e < EE; e++) { p[e] = expf(logits[e] - mx); se += p[e]; }
        const float inv = 1.f / se;
        #pragma unroll
        for (int e = 0; e < EE; e++) p[e] *= inv;
        int e0 = 0;
        #pragma unroll
        for (int e = 1; e < EE; e++) if (p[e] > p[e0]) e0 = e;
        int e1 = (e0 == 0) ? 1 : 0;
        #pragma unroll
        for (int e = 0; e < EE; e++) if (e != e0 && p[e] > p[e1]) e1 = e;
        const float z = expf(p[e1] - p[e0]);
        g_pw[2 * t]     = 1.f / (1.f + z);
        g_pw[2 * t + 1] = z / (1.f + z);
        int i0 = atomicAdd(&g_count[e0], 1);
        g_arows[e0 * NT + i0] = t;
        g_crows[e0 * NT + i0] = 2 * t;
        int i1 = atomicAdd(&g_count[e1], 1);
        g_arows[e1 * NT + i1] = t;
        g_crows[e1 * NT + i1] = 2 * t + 1;
    }
}

__global__ void offsets_kernel() {
    if (threadIdx.x == 0) {
        int a = 0;
        #pragma unroll
        for (int e = 0; e < EE; e++) { g_off[e] = a; a += g_count[e]; }
    }
}

// ---------------- fused gating+up GEMM ---------------------------------------
// H[g_off[e]+slot][n] = tf32(pw * silu(x@Wg) * (x@Wu)),  tile 128x128, K=1024.
__global__ __launch_bounds__(256, 1)
void moe_gu_kernel() {
    const int e = blockIdx.z;
    const int M = g_count[e];
    const int m0 = blockIdx.y * 128;
    if (m0 >= M) return;
    const int n0 = blockIdx.x * 128;

    extern __shared__ float sm[];
    const int tid = threadIdx.x;
    const int wid = tid >> 5, lane = tid & 31;
    const int g = lane >> 2, t4 = lane & 3;
    const int wm = wid & 1, wn = wid >> 1;   // warp tile: rows wm*64, cols wn*32

    const int* arows = g_arows + e * NT;
    const float* Bg = g_Wg + (size_t)e * DD * FF;
    const float* Bu = g_Wu + (size_t)e * DD * FF;

    // loader addresses (per thread: 2x A, 2x Bg, 2x Bu float4 per stage)
    const uint32_t smb = smem_u32(sm);
    const int a_r = tid >> 2, a_c = (tid & 3) * 4;
    const float* ga1 = g_X + (size_t)arows[min(m0 + a_r, M - 1)] * DD + a_c;
    const float* ga2 = g_X + (size_t)arows[min(m0 + a_r + 64, M - 1)] * DD + a_c;
    const uint32_t sa1 = smb + (a_r * 20 + a_c) * 4;
    const uint32_t sa2 = sa1 + 64 * 20 * 4;
    const int b_k = tid >> 5, b_c = (tid & 31) * 4;
    const float* gg1 = Bg + (size_t)b_k * FF + n0 + b_c;
    const float* gg2 = gg1 + (size_t)8 * FF;
    const float* gu1 = Bu + (size_t)b_k * FF + n0 + b_c;
    const float* gu2 = gu1 + (size_t)8 * FF;
    const uint32_t sg1 = smb + (A_SZ + b_k * 136 + b_c) * 4;
    const uint32_t sg2 = sg1 + 8 * 136 * 4;
    const uint32_t su1 = smb + (A_SZ + BGU_SZ + b_k * 136 + b_c) * 4;
    const uint32_t su2 = su1 + 8 * 136 * 4;

    #pragma unroll
    for (int s = 0; s < NSTG - 1; s++) {
        const int kof = s * BK;
        const uint32_t so = s * STG_GU * 4;
        CP_ASYNC16(sa1 + so, ga1 + kof);
        CP_ASYNC16(sa2 + so, ga2 + kof);
        CP_ASYNC16(sg1 + so, gg1 + (size_t)kof * FF);
        CP_ASYNC16(sg2 + so, gg2 + (size_t)kof * FF);
        CP_ASYNC16(su1 + so, gu1 + (size_t)kof * FF);
        CP_ASYNC16(su2 + so, gu2 + (size_t)kof * FF);
        CP_COMMIT();
    }

    float accG[4][4][4], accU[4][4][4];
    #pragma unroll
    for (int i = 0; i < 4; i++)
        #pragma unroll
        for (int j = 0; j < 4; j++)
            #pragma unroll
            for (int q = 0; q < 4; q++) { accG[i][j][q] = 0.f; accU[i][j][q] = 0.f; }

    for (int kt = 0; kt < KT_GU; kt++) {
        CP_WAIT2();
        __syncthreads();
        {
            const int kn = kt + NSTG - 1;
            if (kn < KT_GU) {
                const int kof = kn * BK;
                const uint32_t so = (kn & (NSTG - 1)) * STG_GU * 4;
                CP_ASYNC16(sa1 + so, ga1 + kof);
                CP_ASYNC16(sa2 + so, ga2 + kof);
                CP_ASYNC16(sg1 + so, gg1 + (size_t)kof * FF);
                CP_ASYNC16(sg2 + so, gg2 + (size_t)kof * FF);
                CP_ASYNC16(su1 + so, gu1 + (size_t)kof * FF);
                CP_ASYNC16(su2 + so, gu2 + (size_t)kof * FF);
            }
            CP_COMMIT();
        }
        const float* as = sm + (kt & (NSTG - 1)) * STG_GU;
        const float* bgs = as + A_SZ;
        const float* bus = bgs + BGU_SZ;
        #pragma unroll
        for (int kk = 0; kk < BK; kk += 8) {
            uint32_t af[4][4];
            #pragma unroll
            for (int mf = 0; mf < 4; mf++) {
                const int rb = wm * 64 + mf * 16 + g;
                af[mf][0] = ldsf(as + rb * 20 + kk + t4);
                af[mf][1] = ldsf(as + (rb + 8) * 20 + kk + t4);
                af[mf][2] = ldsf(as + rb * 20 + kk + t4 + 4);
                af[mf][3] = ldsf(as + (rb + 8) * 20 + kk + t4 + 4);
            }
            #pragma unroll
            for (int nf = 0; nf < 4; nf++) {
                const int cb = wn * 32 + nf * 8 + g;
                const uint32_t bg0 = ldsf(bgs + (kk + t4) * 136 + cb);
                const uint32_t bg1 = ldsf(bgs + (kk + t4 + 4) * 136 + cb);
                const uint32_t bu0 = ldsf(bus + (kk + t4) * 136 + cb);
                const uint32_t bu1 = ldsf(bus + (kk + t4 + 4) * 136 + cb);
                #pragma unroll
                for (int mf = 0; mf < 4; mf++) {
                    mma_tf32(accG[mf][nf], af[mf], bg0, bg1);
                    mma_tf32(accU[mf][nf], af[mf], bu0, bu1);
                }
            }
        }
    }

    // epilogue: h = tf32(pw * silu(g) * u) -> g_H[g_off[e]+slot]
    const int hbase = g_off[e];
    const int* crows = g_crows + e * NT;
    #pragma unroll
    for (int mf = 0; mf < 4; mf++) {
        const int r_lo = m0 + wm * 64 + mf * 16 + g;
        const int r_hi = r_lo + 8;
        const bool v_lo = r_lo < M, v_hi = r_hi < M;
        const float pw_lo = v_lo ? g_pw[crows[r_lo]] : 0.f;
        const float pw_hi = v_hi ? g_pw[crows[r_hi]] : 0.f;
        float* h_lo = g_H + (size_t)(hbase + (v_lo ? r_lo : 0)) * FF;
        float* h_hi = g_H + (size_t)(hbase + (v_hi ? r_hi : 0)) * FF;
        #pragma unroll
        for (int nf = 0; nf < 4; nf++) {
            const int cc = n0 + wn * 32 + nf * 8 + t4 * 2;
            if (v_lo) {
                const float gv0 = accG[mf][nf][0], uv0 = accU[mf][nf][0];
                const float gv1 = accG[mf][nf][1], uv1 = accU[mf][nf][1];
                float2 h;
                h.x = __uint_as_float(f2tf(pw_lo * (gv0 / (1.f + __expf(-gv0))) * uv0));
                h.y = __uint_as_float(f2tf(pw_lo * (gv1 / (1.f + __expf(-gv1))) * uv1));
                *(float2*)(h_lo + cc) = h;
            }
            if (v_hi) {
                const float gv0 = accG[mf][nf][2], uv0 = accU[mf][nf][2];
                const float gv1 = accG[mf][nf][3], uv1 = accU[mf][nf][3];
                float2 h;
                h.x = __uint_as_float(f2tf(pw_hi * (gv0 / (1.f + __expf(-gv0))) * uv0));
                h.y = __uint_as_float(f2tf(pw_hi * (gv1 / (1.f + __expf(-gv1))) * uv1));
                *(float2*)(h_hi + cc) = h;
            }
        }
    }
}

// ---------------- down GEMM --------------------------------------------------
// O[crows[slot]][n] = H[g_off[e]+slot][:] @ Wd[e],  tile 128x256, K=2048.
__global__ __launch_bounds__(256, 1)
void moe_dn_kernel() {
    const int e = blockIdx.z;
    const int M = g_count[e];
    const int m0 = blockIdx.y * 128;
    if (m0 >= M) return;
    const int n0 = blockIdx.x * 256;

    extern __shared__ float sm[];
    const int tid = threadIdx.x;
    const int wid = tid >> 5, lane = tid & 31;
    const int g = lane >> 2, t4 = lane & 3;
    const int wm = wid & 1, wn = wid >> 1;   // warp tile: rows wm*64, cols wn*64

    const float* Bd = g_Wd + (size_t)e * FF * DD;
    const int base_row = g_off[e] + m0;

    const uint32_t smb = smem_u32(sm);
    const int a_r = tid >> 2, a_c = (tid & 3) * 4;
    const float* ga1 = g_H + (size_t)min(base_row + a_r, NP - 1) * FF + a_c;
    const float* ga2 = g_H + (size_t)min(base_row + a_r + 64, NP - 1) * FF + a_c;
    const uint32_t sa1 = smb + (a_r * 20 + a_c) * 4;
    const uint32_t sa2 = sa1 + 64 * 20 * 4;
    const int b_k = tid >> 6, b_c = (tid & 63) * 4;   // 4 rows x 64 col4s, x4
    const float* gb = Bd + (size_t)b_k * DD + n0 + b_c;
    const uint32_t sb = smb + (A_SZ + b_k * 264 + b_c) * 4;

    #pragma unroll
    for (int s = 0; s < NSTG - 1; s++) {
        const int kof = s * BK;
        const uint32_t so = s * STG_DN * 4;
        CP_ASYNC16(sa1 + so, ga1 + kof);
        CP_ASYNC16(sa2 + so, ga2 + kof);
        #pragma unroll
        for (int q = 0; q < 4; q++)
            CP_ASYNC16(sb + so + q * 4 * 264 * 4, gb + (size_t)(kof + q * 4) * DD);
        CP_COMMIT();
    }

    float acc[4][8][4];
    #pragma unroll
    for (int i = 0; i < 4; i++)
        #pragma unroll
        for (int j = 0; j < 8; j++)
            #pragma unroll
            for (int q = 0; q < 4; q++) acc[i][j][q] = 0.f;

    for (int kt = 0; kt < KT_DN; kt++) {
        CP_WAIT2();
        __syncthreads();
        {
            const int kn = kt + NSTG - 1;
            if (kn < KT_DN) {
                const int kof = kn * BK;
                const uint32_t so = (kn & (NSTG - 1)) * STG_DN * 4;
                CP_ASYNC16(sa1 + so, ga1 + kof);
                CP_ASYNC16(sa2 + so, ga2 + kof);
                #pragma unroll
                for (int q = 0; q < 4; q++)
                    CP_ASYNC16(sb + so + q * 4 * 264 * 4, gb + (size_t)(kof + q * 4) * DD);
            }
            CP_COMMIT();
        }
        const float* as = sm + (kt & (NSTG - 1)) * STG_DN;
        const float* bs = as + A_SZ;
        #pragma unroll
        for (int kk = 0; kk < BK; kk += 8) {
            uint32_t af[4][4];
            #pragma unroll
            for (int mf = 0; mf < 4; mf++) {
                const int rb = wm * 64 + mf * 16 + g;
                af[mf][0] = ldsf(as + rb * 20 + kk + t4);
                af[mf][1] = ldsf(as + (rb + 8) * 20 + kk + t4);
                af[mf][2] = ldsf(as + rb * 20 + kk + t4 + 4);
                af[mf][3] = ldsf(as + (rb + 8) * 20 + kk + t4 + 4);
            }
            #pragma unroll
            for (int nf = 0; nf < 8; nf++) {
                const int cb = wn * 64 + nf * 8 + g;
                const uint32_t b0 = ldsf(bs + (kk + t4) * 264 + cb);
                const uint32_t b1 = ldsf(bs + (kk + t4 + 4) * 264 + cb);
                #pragma unroll
                for (int mf = 0; mf < 4; mf++)
                    mma_tf32(acc[mf][nf], af[mf], b0, b1);
            }
        }
    }

    const int* crows = g_crows + e * NT;
    #pragma unroll
    for (int mf = 0; mf < 4; mf++) {
        const int r_lo = m0 + wm * 64 + mf * 16 + g;
        const int r_hi = r_lo + 8;
        float* o_lo = (r_lo < M) ? (g_O + (size_t)crows[r_lo] * DD) : nullptr;
        float* o_hi = (r_hi < M) ? (g_O + (size_t)crows[r_hi] * DD) : nullptr;
        #pragma unroll
        for (int nf = 0; nf < 8; nf++) {
            const int cc = n0 + wn * 64 + nf * 8 + t4 * 2;
            if (o_lo) *(float2*)(o_lo + cc) = make_float2(acc[mf][nf][0], acc[mf][nf][1]);
            if (o_hi) *(float2*)(o_hi + cc) = make_float2(acc[mf][nf][2], acc[mf][nf][3]);
        }
    }
}

// ---------------- combine: out[t] = O[2t] + O[2t+1] ---------------------------
__global__ void combine_kernel(float* __restrict__ out) {
    const size_t i = (size_t)blockIdx.x * blockDim.x + threadIdx.x;
    const size_t t = i / (DD / 4);
    const size_t c = i % (DD / 4);
    const float4 a = ((const float4*)g_O)[t * 2 * (DD / 4) + c];
    const float4 b = ((const float4*)g_O)[(t * 2 + 1) * (DD / 4) + c];
    ((float4*)out)[i] = make_float4(a.x + b.x, a.y + b.y, a.z + b.z, a.w + b.w);
}

// ---------------- launcher ---------------------------------------------------
extern "C" void kernel_launch(void* const* d_in, const int* in_sizes, int n_in,
                              void* d_out, int out_size) {
    const float* x  = (const float*)d_in[0];
    const float* Wr = (const float*)d_in[1];
    const float* Wg = (const float*)d_in[2];
    const float* Wu = (const float*)d_in[3];
    const float* Wd = (const float*)d_in[4];
    float* out = (float*)d_out;

    cudaFuncSetAttribute(moe_gu_kernel, cudaFuncAttributeMaxDynamicSharedMemorySize, GU_SMEM);
    cudaFuncSetAttribute(moe_dn_kernel, cudaFuncAttributeMaxDynamicSharedMemorySize, DN_SMEM);

    float* X; float* Gw; float* Uw; float* Dw;
    cudaGetSymbolAddress((void**)&X,  g_X);
    cudaGetSymbolAddress((void**)&Gw, g_Wg);
    cudaGetSymbolAddress((void**)&Uw, g_Wu);
    cudaGetSymbolAddress((void**)&Dw, g_Wd);

    zero_counts_kernel<<<1, 32>>>();
    router_kernel<<<NT, 256>>>(x, Wr);
    offsets_kernel<<<1, 32>>>();

    // tf32 pre-conversion (RNA)
    cvt_kernel<<<(int)(((size_t)NT * DD / 4) / 256), 256>>>((const float4*)x, (float4*)X);
    cvt_kernel<<<(int)(((size_t)EE * DD * FF / 4) / 256), 256>>>((const float4*)Wg, (float4*)Gw);
    cvt_kernel<<<(int)(((size_t)EE * DD * FF / 4) / 256), 256>>>((const float4*)Wu, (float4*)Uw);
    cvt_kernel<<<(int)(((size_t)EE * FF * DD / 4) / 256), 256>>>((const float4*)Wd, (float4*)Dw);

    moe_gu_kernel<<<dim3(FF / 128, 32, EE), 256, GU_SMEM>>>();
    moe_dn_kernel<<<dim3(DD / 256, 32, EE), 256, DN_SMEM>>>();

    combine_kernel<<<(int)(((size_t)NT * DD / 4) / 256), 256>>>(out);
}

// round 5
// speedup vs baseline: 6.6912x; 2.0250x over previous
#include <cuda_runtime.h>
#include <cuda_fp16.h>
#include <cuda_bf16.h>
#include <math.h>
#include <stdint.h>

// Problem dims: B=2, T=2048 -> NT=4096 tokens, D=1024, E=8, F=2048, top-2 -> NP=8192 pairs.
#define NT 4096
#define DD 1024
#define EE 8
#define FF 2048
#define NP (NT * 2)

#define BKH 32          // k per stage (halves)
#define NSTG 4
#define A_STG_B 8192    // 128 rows x 32 halves x 2B
#define B_STG_B 8192    // 32 rows x 128 halves x 2B
#define GU_STG (A_STG_B + 2 * B_STG_B)   // 24576
#define GU_SMEM (NSTG * GU_STG)          // 98304
#define DN_STG (A_STG_B + B_STG_B)       // 16384
#define DN_SMEM (NSTG * DN_STG)          // 65536
#define KT_GU (DD / BKH)   // 32
#define KT_DN (FF / BKH)   // 64

// ---------------- static scratch ----------------
__device__ int    g_count[EE];
__device__ int    g_off[EE];
__device__ int    g_arows[EE * NT];
__device__ int    g_crows[EE * NT];
__device__ float  g_pw[NP];
__device__ __half g_Xh [(size_t)NT * DD];
__device__ __half g_Wgh[(size_t)EE * DD * FF];
__device__ __half g_Wuh[(size_t)EE * DD * FF];
__device__ __half g_Wdh[(size_t)EE * FF * DD];
__device__ __half g_Hh [(size_t)NP * FF];      // compact per-expert H rows
__device__ float  g_O  [(size_t)NP * DD];

// ---------------- helpers ----------------
__device__ __forceinline__ uint32_t smem_u32(const void* p) {
    uint32_t a;
    asm("{ .reg .u64 t; cvta.to.shared.u64 t, %1; cvt.u32.u64 %0, t; }" : "=r"(a) : "l"(p));
    return a;
}
#define CP_ASYNC16(sdst, gsrc) \
    asm volatile("cp.async.cg.shared.global [%0], [%1], 16;" :: "r"(sdst), "l"(gsrc) : "memory")
#define CP_COMMIT() asm volatile("cp.async.commit_group;" ::: "memory")
#define CP_WAIT2()  asm volatile("cp.async.wait_group 2;" ::: "memory")

#define LDMX4(r0, r1, r2, r3, addr) \
    asm volatile("ldmatrix.sync.aligned.m8n8.x4.shared.b16 {%0,%1,%2,%3}, [%4];" \
                 : "=r"(r0), "=r"(r1), "=r"(r2), "=r"(r3) : "r"(addr))
#define LDMX4T(r0, r1, r2, r3, addr) \
    asm volatile("ldmatrix.sync.aligned.m8n8.x4.trans.shared.b16 {%0,%1,%2,%3}, [%4];" \
                 : "=r"(r0), "=r"(r1), "=r"(r2), "=r"(r3) : "r"(addr))

__device__ __forceinline__ void mma_f16(float* c, const uint32_t* a, uint32_t b0, uint32_t b1) {
    asm volatile(
        "mma.sync.aligned.m16n8k16.row.col.f32.f16.f16.f32 "
        "{%0,%1,%2,%3}, {%4,%5,%6,%7}, {%8,%9}, {%0,%1,%2,%3};"
        : "+f"(c[0]), "+f"(c[1]), "+f"(c[2]), "+f"(c[3])
        : "r"(a[0]), "r"(a[1]), "r"(a[2]), "r"(a[3]), "r"(b0), "r"(b1));
}

// ---------------- fp32 -> fp16 convert (8 elems/thread) ----------------
__global__ void cvt_h_kernel(const float4* __restrict__ in, uint4* __restrict__ out) {
    const size_t i = (size_t)blockIdx.x * blockDim.x + threadIdx.x;
    const float4 a = in[2 * i], b = in[2 * i + 1];
    __half2 h0 = __floats2half2_rn(a.x, a.y);
    __half2 h1 = __floats2half2_rn(a.z, a.w);
    __half2 h2 = __floats2half2_rn(b.x, b.y);
    __half2 h3 = __floats2half2_rn(b.z, b.w);
    uint4 o;
    o.x = *reinterpret_cast<uint32_t*>(&h0);
    o.y = *reinterpret_cast<uint32_t*>(&h1);
    o.z = *reinterpret_cast<uint32_t*>(&h2);
    o.w = *reinterpret_cast<uint32_t*>(&h3);
    out[i] = o;
}

// ---------------- router path ----------------
__global__ void zero_counts_kernel() {
    if (threadIdx.x < EE) g_count[threadIdx.x] = 0;
}

__global__ void router_kernel(const float* __restrict__ x,
                              const float* __restrict__ Wr) {
    __shared__ float xs[DD];
    __shared__ float logits[EE];
    const int t = blockIdx.x;
    const int tid = threadIdx.x;
    const float* xr = x + (size_t)t * DD;
    *(float4*)&xs[tid * 4] = *(const float4*)&xr[tid * 4];
    __syncthreads();

    const int w = tid >> 5, lane = tid & 31;
    float s = 0.f;
    #pragma unroll 8
    for (int d = lane; d < DD; d += 32) s += xs[d] * Wr[d * EE + w];
    #pragma unroll
    for (int o = 16; o; o >>= 1) s += __shfl_xor_sync(0xffffffffu, s, o);
    if (lane == 0) logits[w] = s;
    __syncthreads();

    if (tid == 0) {
        float mx = logits[0];
        #pragma unroll
        for (int e = 1; e < EE; e++) mx = fmaxf(mx, logits[e]);
        float p[EE], se = 0.f;
        #pragma unroll
        for (int e = 0; e < EE; e++) { p[e] = expf(logits[e] - mx); se += p[e]; }
        const float inv = 1.f / se;
        #pragma unroll
        for (int e = 0; e < EE; e++) p[e] *= inv;
        int e0 = 0;
        #pragma unroll
        for (int e = 1; e < EE; e++) if (p[e] > p[e0]) e0 = e;
        int e1 = (e0 == 0) ? 1 : 0;
        #pragma unroll
        for (int e = 0; e < EE; e++) if (e != e0 && p[e] > p[e1]) e1 = e;
        const float z = expf(p[e1] - p[e0]);
        g_pw[2 * t]     = 1.f / (1.f + z);
        g_pw[2 * t + 1] = z / (1.f + z);
        int i0 = atomicAdd(&g_count[e0], 1);
        g_arows[e0 * NT + i0] = t;
        g_crows[e0 * NT + i0] = 2 * t;
        int i1 = atomicAdd(&g_count[e1], 1);
        g_arows[e1 * NT + i1] = t;
        g_crows[e1 * NT + i1] = 2 * t + 1;
    }
}

__global__ void offsets_kernel() {
    if (threadIdx.x == 0) {
        int a = 0;
        #pragma unroll
        for (int e = 0; e < EE; e++) { g_off[e] = a; a += g_count[e]; }
    }
}

// A tile smem address: row r (0..127, 64B rows), 16B group cg (0..3), XOR swizzle
__device__ __forceinline__ uint32_t a_smaddr(uint32_t st, int r, int cg) {
    return st + r * 64 + (((uint32_t)cg ^ (((uint32_t)r >> 1) & 3)) << 4);
}
// B tile smem address: k row (0..31, 256B rows), 16B group ng (0..15)
__device__ __forceinline__ uint32_t b_smaddr(uint32_t st, int k, int ng) {
    return st + k * 256 + (((uint32_t)ng ^ ((uint32_t)k & 7)) << 4);
}

// ---------------- fused gating+up fp16 GEMM ----------------------------------
// H[g_off[e]+slot][n] = half(pw * silu(x@Wg) * (x@Wu)),  tile 128x128, K=1024.
__global__ __launch_bounds__(256, 1)
void moe_gu_kernel() {
    const int e = blockIdx.z;
    const int M = g_count[e];
    const int m0 = blockIdx.y * 128;
    if (m0 >= M) return;
    const int n0 = blockIdx.x * 128;

    extern __shared__ char sm[];
    const uint32_t smb = smem_u32(sm);
    const int tid = threadIdx.x;
    const int wid = tid >> 5, lane = tid & 31;
    const int g = lane >> 2, t4 = lane & 3;
    const int wm = wid & 1, wn = wid >> 1;      // warp tile rows wm*64, cols wn*32
    const int lrow = lane & 7, quad = lane >> 3;
    const int frow = ((quad & 1) << 3) + lrow;  // row within 16-row fragment
    const int kgi = quad >> 1;                  // k 16B-group within k16
    const int ngq = quad >> 1;                  // n 16B-group offset

    const int* arows = g_arows + e * NT;
    const __half* Bg = g_Wgh + (size_t)e * DD * FF;
    const __half* Bu = g_Wuh + (size_t)e * DD * FF;

    // ---- loader setup: per stage 2 A + 2 Bg + 2 Bu 16B groups per thread ----
    const __half* gA[2]; uint32_t sA[2];
    #pragma unroll
    for (int j = 0; j < 2; j++) {
        const int idx = tid + j * 256;
        const int r = idx >> 2, cg = idx & 3;
        gA[j] = g_Xh + (size_t)arows[min(m0 + r, M - 1)] * DD + cg * 8;
        sA[j] = a_smaddr(smb, r, cg);
    }
    const __half* gG[2]; const __half* gU[2]; uint32_t sG[2], sU[2];
    #pragma unroll
    for (int j = 0; j < 2; j++) {
        const int idx = tid + j * 256;
        const int k = idx >> 4, ng = idx & 15;
        gG[j] = Bg + (size_t)k * FF + n0 + ng * 8;
        gU[j] = Bu + (size_t)k * FF + n0 + ng * 8;
        sG[j] = b_smaddr(smb + A_STG_B, k, ng);
        sU[j] = b_smaddr(smb + A_STG_B + B_STG_B, k, ng);
    }

    #pragma unroll
    for (int s = 0; s < NSTG - 1; s++) {
        const int kof = s * BKH;
        const uint32_t so = s * GU_STG;
        #pragma unroll
        for (int j = 0; j < 2; j++) {
            CP_ASYNC16(sA[j] + so, gA[j] + kof);
            CP_ASYNC16(sG[j] + so, gG[j] + (size_t)kof * FF);
            CP_ASYNC16(sU[j] + so, gU[j] + (size_t)kof * FF);
        }
        CP_COMMIT();
    }

    float accG[4][4][4], accU[4][4][4];
    #pragma unroll
    for (int i = 0; i < 4; i++)
        #pragma unroll
        for (int j = 0; j < 4; j++)
            #pragma unroll
            for (int q = 0; q < 4; q++) { accG[i][j][q] = 0.f; accU[i][j][q] = 0.f; }

    for (int kt = 0; kt < KT_GU; kt++) {
        CP_WAIT2();
        __syncthreads();
        {
            const int kn = kt + NSTG - 1;
            if (kn < KT_GU) {
                const int kof = kn * BKH;
                const uint32_t so = (kn & (NSTG - 1)) * GU_STG;
                #pragma unroll
                for (int j = 0; j < 2; j++) {
                    CP_ASYNC16(sA[j] + so, gA[j] + kof);
                    CP_ASYNC16(sG[j] + so, gG[j] + (size_t)kof * FF);
                    CP_ASYNC16(sU[j] + so, gU[j] + (size_t)kof * FF);
                }
            }
            CP_COMMIT();
        }
        const uint32_t stA = smb + (kt & (NSTG - 1)) * GU_STG;
        const uint32_t stG = stA + A_STG_B;
        const uint32_t stU = stG + B_STG_B;
        #pragma unroll
        for (int kk = 0; kk < 2; kk++) {
            uint32_t af[4][4];
            #pragma unroll
            for (int mf = 0; mf < 4; mf++) {
                const int r = wm * 64 + mf * 16 + frow;
                LDMX4(af[mf][0], af[mf][1], af[mf][2], af[mf][3],
                      a_smaddr(stA, r, kk * 2 + kgi));
            }
            uint32_t bg[2][4], bu[2][4];
            #pragma unroll
            for (int w16 = 0; w16 < 2; w16++) {
                const int k = kk * 16 + ((quad & 1) << 3) + lrow;
                const int ng = wn * 4 + w16 * 2 + ngq;
                LDMX4T(bg[w16][0], bg[w16][1], bg[w16][2], bg[w16][3],
                       b_smaddr(stG, k, ng));
                LDMX4T(bu[w16][0], bu[w16][1], bu[w16][2], bu[w16][3],
                       b_smaddr(stU, k, ng));
            }
            #pragma unroll
            for (int nf = 0; nf < 4; nf++) {
                const int w16 = nf >> 1, sl = (nf & 1) * 2;
                #pragma unroll
                for (int mf = 0; mf < 4; mf++) {
                    mma_f16(accG[mf][nf], af[mf], bg[w16][sl], bg[w16][sl + 1]);
                    mma_f16(accU[mf][nf], af[mf], bu[w16][sl], bu[w16][sl + 1]);
                }
            }
        }
    }

    // epilogue: h = half(pw * silu(g) * u) -> g_Hh[g_off[e]+slot]
    const int hbase = g_off[e];
    const int* crows = g_crows + e * NT;
    #pragma unroll
    for (int mf = 0; mf < 4; mf++) {
        const int r_lo = m0 + wm * 64 + mf * 16 + g;
        const int r_hi = r_lo + 8;
        const bool v_lo = r_lo < M, v_hi = r_hi < M;
        const float pw_lo = v_lo ? g_pw[crows[r_lo]] : 0.f;
        const float pw_hi = v_hi ? g_pw[crows[r_hi]] : 0.f;
        __half* h_lo = g_Hh + (size_t)(hbase + (v_lo ? r_lo : 0)) * FF;
        __half* h_hi = g_Hh + (size_t)(hbase + (v_hi ? r_hi : 0)) * FF;
        #pragma unroll
        for (int nf = 0; nf < 4; nf++) {
            const int cc = n0 + wn * 32 + nf * 8 + t4 * 2;
            if (v_lo) {
                const float g0 = accG[mf][nf][0], u0 = accU[mf][nf][0];
                const float g1 = accG[mf][nf][1], u1 = accU[mf][nf][1];
                *(__half2*)(h_lo + cc) = __floats2half2_rn(
                    pw_lo * (g0 / (1.f + __expf(-g0))) * u0,
                    pw_lo * (g1 / (1.f + __expf(-g1))) * u1);
            }
            if (v_hi) {
                const float g0 = accG[mf][nf][2], u0 = accU[mf][nf][2];
                const float g1 = accG[mf][nf][3], u1 = accU[mf][nf][3];
                *(__half2*)(h_hi + cc) = __floats2half2_rn(
                    pw_hi * (g0 / (1.f + __expf(-g0))) * u0,
                    pw_hi * (g1 / (1.f + __expf(-g1))) * u1);
            }
        }
    }
}

// ---------------- down fp16 GEMM ---------------------------------------------
// O[crows[slot]][n] = H[g_off[e]+slot][:] @ Wd[e],  tile 128x128, K=2048.
__global__ __launch_bounds__(256, 2)
void moe_dn_kernel() {
    const int e = blockIdx.z;
    const int M = g_count[e];
    const int m0 = blockIdx.y * 128;
    if (m0 >= M) return;
    const int n0 = blockIdx.x * 128;

    extern __shared__ char sm[];
    const uint32_t smb = smem_u32(sm);
    const int tid = threadIdx.x;
    const int wid = tid >> 5, lane = tid & 31;
    const int g = lane >> 2, t4 = lane & 3;
    const int wm = wid & 1, wn = wid >> 1;
    const int lrow = lane & 7, quad = lane >> 3;
    const int frow = ((quad & 1) << 3) + lrow;
    const int kgi = quad >> 1;
    const int ngq = quad >> 1;

    const __half* Bd = g_Wdh + (size_t)e * FF * DD;
    const int base_row = g_off[e] + m0;

    const __half* gA[2]; uint32_t sA[2];
    #pragma unroll
    for (int j = 0; j < 2; j++) {
        const int idx = tid + j * 256;
        const int r = idx >> 2, cg = idx & 3;
        gA[j] = g_Hh + (size_t)min(base_row + r, NP - 1) * FF + cg * 8;
        sA[j] = a_smaddr(smb, r, cg);
    }
    const __half* gB[2]; uint32_t sB[2];
    #pragma unroll
    for (int j = 0; j < 2; j++) {
        const int idx = tid + j * 256;
        const int k = idx >> 4, ng = idx & 15;
        gB[j] = Bd + (size_t)k * DD + n0 + ng * 8;
        sB[j] = b_smaddr(smb + A_STG_B, k, ng);
    }

    #pragma unroll
    for (int s = 0; s < NSTG - 1; s++) {
        const int kof = s * BKH;
        const uint32_t so = s * DN_STG;
        #pragma unroll
        for (int j = 0; j < 2; j++) {
            CP_ASYNC16(sA[j] + so, gA[j] + kof);
            CP_ASYNC16(sB[j] + so, gB[j] + (size_t)kof * DD);
        }
        CP_COMMIT();
    }

    float acc[4][4][4];
    #pragma unroll
    for (int i = 0; i < 4; i++)
        #pragma unroll
        for (int j = 0; j < 4; j++)
            #pragma unroll
            for (int q = 0; q < 4; q++) acc[i][j][q] = 0.f;

    for (int kt = 0; kt < KT_DN; kt++) {
        CP_WAIT2();
        __syncthreads();
        {
            const int kn = kt + NSTG - 1;
            if (kn < KT_DN) {
                const int kof = kn * BKH;
                const uint32_t so = (kn & (NSTG - 1)) * DN_STG;
                #pragma unroll
                for (int j = 0; j < 2; j++) {
                    CP_ASYNC16(sA[j] + so, gA[j] + kof);
                    CP_ASYNC16(sB[j] + so, gB[j] + (size_t)kof * DD);
                }
            }
            CP_COMMIT();
        }
        const uint32_t stA = smb + (kt & (NSTG - 1)) * DN_STG;
        const uint32_t stB = stA + A_STG_B;
        #pragma unroll
        for (int kk = 0; kk < 2; kk++) {
            uint32_t af[4][4];
            #pragma unroll
            for (int mf = 0; mf < 4; mf++) {
                const int r = wm * 64 + mf * 16 + frow;
                LDMX4(af[mf][0], af[mf][1], af[mf][2], af[mf][3],
                      a_smaddr(stA, r, kk * 2 + kgi));
            }
            uint32_t bb[2][4];
            #pragma unroll
            for (int w16 = 0; w16 < 2; w16++) {
                const int k = kk * 16 + ((quad & 1) << 3) + lrow;
                const int ng = wn * 4 + w16 * 2 + ngq;
                LDMX4T(bb[w16][0], bb[w16][1], bb[w16][2], bb[w16][3],
                       b_smaddr(stB, k, ng));
            }
            #pragma unroll
            for (int nf = 0; nf < 4; nf++) {
                const int w16 = nf >> 1, sl = (nf & 1) * 2;
                #pragma unroll
                for (int mf = 0; mf < 4; mf++)
                    mma_f16(acc[mf][nf], af[mf], bb[w16][sl], bb[w16][sl + 1]);
            }
        }
    }

    const int* crows = g_crows + e * NT;
    #pragma unroll
    for (int mf = 0; mf < 4; mf++) {
        const int r_lo = m0 + wm * 64 + mf * 16 + g;
        const int r_hi = r_lo + 8;
        float* o_lo = (r_lo < M) ? (g_O + (size_t)crows[r_lo] * DD) : nullptr;
        float* o_hi = (r_hi < M) ? (g_O + (size_t)crows[r_hi] * DD) : nullptr;
        #pragma unroll
        for (int nf = 0; nf < 4; nf++) {
            const int cc = n0 + wn * 32 + nf * 8 + t4 * 2;
            if (o_lo) *(float2*)(o_lo + cc) = make_float2(acc[mf][nf][0], acc[mf][nf][1]);
            if (o_hi) *(float2*)(o_hi + cc) = make_float2(acc[mf][nf][2], acc[mf][nf][3]);
        }
    }
}

// ---------------- combine: out[t] = O[2t] + O[2t+1] ---------------------------
__global__ void combine_kernel(float* __restrict__ out) {
    const size_t i = (size_t)blockIdx.x * blockDim.x + threadIdx.x;
    const size_t t = i / (DD / 4);
    const size_t c = i % (DD / 4);
    const float4 a = ((const float4*)g_O)[t * 2 * (DD / 4) + c];
    const float4 b = ((const float4*)g_O)[(t * 2 + 1) * (DD / 4) + c];
    ((float4*)out)[i] = make_float4(a.x + b.x, a.y + b.y, a.z + b.z, a.w + b.w);
}

// ---------------- launcher ---------------------------------------------------
extern "C" void kernel_launch(void* const* d_in, const int* in_sizes, int n_in,
                              void* d_out, int out_size) {
    const float* x  = (const float*)d_in[0];
    const float* Wr = (const float*)d_in[1];
    const float* Wg = (const float*)d_in[2];
    const float* Wu = (const float*)d_in[3];
    const float* Wd = (const float*)d_in[4];
    float* out = (float*)d_out;

    cudaFuncSetAttribute(moe_gu_kernel, cudaFuncAttributeMaxDynamicSharedMemorySize, GU_SMEM);
    cudaFuncSetAttribute(moe_dn_kernel, cudaFuncAttributeMaxDynamicSharedMemorySize, DN_SMEM);

    __half* Xh; __half* Gh; __half* Uh; __half* Dh;
    cudaGetSymbolAddress((void**)&Xh, g_Xh);
    cudaGetSymbolAddress((void**)&Gh, g_Wgh);
    cudaGetSymbolAddress((void**)&Uh, g_Wuh);
    cudaGetSymbolAddress((void**)&Dh, g_Wdh);

    zero_counts_kernel<<<1, 32>>>();
    router_kernel<<<NT, 256>>>(x, Wr);
    offsets_kernel<<<1, 32>>>();

    cvt_h_kernel<<<(int)(((size_t)NT * DD / 8) / 256), 256>>>((const float4*)x, (uint4*)Xh);
    cvt_h_kernel<<<(int)(((size_t)EE * DD * FF / 8) / 256), 256>>>((const float4*)Wg, (uint4*)Gh);
    cvt_h_kernel<<<(int)(((size_t)EE * DD * FF / 8) / 256), 256>>>((const float4*)Wu, (uint4*)Uh);
    cvt_h_kernel<<<(int)(((size_t)EE * FF * DD / 8) / 256), 256>>>((const float4*)Wd, (uint4*)Dh);

    moe_gu_kernel<<<dim3(FF / 128, 32, EE), 256, GU_SMEM>>>();
    moe_dn_kernel<<<dim3(DD / 128, 32, EE), 256, DN_SMEM>>>();

    combine_kernel<<<(int)(((size_t)NT * DD / 4) / 256), 256>>>(out);
}